// round 8
// baseline (speedup 1.0000x reference)
#include <cuda_runtime.h>
#include <math.h>
#include <stdint.h>

// Problem constants
#define Bb 128
#define Tt 1024
#define Ll 2
#define Dd 512
#define Hh 512
#define G4 2048   // 4*H
#define Kc 1024   // combined K = D + H

// Tile config
#define BM 64
#define NH 16
#define BN 64
#define KT 32
#define NT2 16           // k-iterations per kgroup (512 / 32)
#define NBLOCKS 128
#define ZST 68
#define THREADS 512

// Shared memory layout (floats), dynamic
#define A_TILE_F 392               // per m16xk8 tile: 32 lanes * 12 (+ pad)
#define A_BUF_F  (16 * A_TILE_F)   // 16 tiles (4 m16 x 4 k8) = 6272
#define B_ROW_F  136               // 64 cols * 2 (hi,lo) + 8 pad
#define B_BUF_F  (KT * B_ROW_F)    // 4352
#define OFF_B0   (2 * A_BUF_F)     // 12544 (within a kgroup region)
#define KG_STRIDE (2 * A_BUF_F + 2 * B_BUF_F)   // 21248 floats per kgroup
#define SMEM_F   (2 * KG_STRIDE)                // 42496 floats
#define SMEM_BYTES (SMEM_F * 4)                 // 169984 B

// Persistent device state
__device__ float g_h[Ll][2][Bb][Hh];      // double-buffered h (parity = t&1 in)
__device__ float g_hbuf[2][Bb][Hh];       // layer-0 unmasked nh stream
__device__ float g_Wint[Ll][Kc][G4][2];   // weights, tf32 {hi,lo} interleaved
__device__ unsigned int g_bar_count;
__device__ unsigned int g_bar_phase;

__device__ __forceinline__ float sigf(float v) { return 1.0f / (1.0f + __expf(-v)); }

__device__ __forceinline__ float tf32f(float x) {
    uint32_t u;
    asm("cvt.rna.tf32.f32 %0, %1;" : "=r"(u) : "f"(x));
    return __uint_as_float(u);
}

__device__ __forceinline__ void mma8(float* c, const uint32_t* a, const uint32_t* b) {
    asm volatile(
        "mma.sync.aligned.m16n8k8.row.col.f32.tf32.tf32.f32 "
        "{%0,%1,%2,%3}, {%4,%5,%6,%7}, {%8,%9}, {%0,%1,%2,%3};"
        : "+f"(c[0]), "+f"(c[1]), "+f"(c[2]), "+f"(c[3])
        : "r"(a[0]), "r"(a[1]), "r"(a[2]), "r"(a[3]), "r"(b[0]), "r"(b[1]));
}

__device__ __forceinline__ void cpa16(uint32_t dst, const void* src) {
    asm volatile("cp.async.cg.shared.global [%0], [%1], 16;" :: "r"(dst), "l"(src));
}

__device__ __forceinline__ void grid_barrier(unsigned int target) {
    __syncthreads();
    if (threadIdx.x == 0) {
        __threadfence();
        unsigned int old = atomicAdd(&g_bar_count, 1u);
        if (old == NBLOCKS - 1) {
            g_bar_count = 0;
            __threadfence();
            atomicAdd(&g_bar_phase, 1u);
        } else {
            while (*(volatile unsigned int*)&g_bar_phase < target) { }
            __threadfence();
        }
    }
    __syncthreads();
}

extern __shared__ float smem[];

__global__ void __launch_bounds__(THREADS, 1)
lstm_persistent(const float* __restrict__ x,
                const float* __restrict__ h_masks,
                const float* __restrict__ Wi,
                const float* __restrict__ Wh,
                const float* __restrict__ bias,
                const float* __restrict__ c0,
                const float* __restrict__ h0,
                const int*   __restrict__ lengths,
                float* __restrict__ out)
{
    __shared__ unsigned int s_base;

    const int tid   = threadIdx.x;
    const int layer = blockIdx.z;
    const int j0    = blockIdx.x * NH;
    const int m0    = blockIdx.y * BM;
    const int gb    = (blockIdx.z * gridDim.y + blockIdx.y) * gridDim.x + blockIdx.x;
    const int gtid  = gb * THREADS + tid;

    if (tid == 0) s_base = *(volatile unsigned int*)&g_bar_phase;

    // ---- one-time init: h state + interleaved split weights ----
    {
        const int total = Ll * Bb * Hh;
        for (int i = gtid; i < total; i += NBLOCKS * THREADS) {
            const int l = i / (Bb * Hh);
            const int r = i % (Bb * Hh);
            (&g_h[l][0][0][0])[r] = h0[i];
        }
        float* Wflat = &g_Wint[0][0][0][0];
        const int totalW = Ll * Kc * G4;   // 2^22
        for (int i = gtid; i < totalW; i += NBLOCKS * THREADS) {
            const int l = i >> 21;
            const int r = i & ((1 << 21) - 1);
            const int k = r >> 11;
            const int c = r & (G4 - 1);
            float w = (k < Dd) ? Wi[(size_t)l * Dd * G4 + (size_t)k * G4 + c]
                               : Wh[(size_t)l * Hh * G4 + (size_t)(k - Dd) * G4 + c];
            float hi = tf32f(w);
            *(float2*)(Wflat + (size_t)i * 2) = make_float2(hi, tf32f(w - hi));
        }
    }
    __syncthreads();
    const unsigned int base = s_base;
    unsigned int bar = 1;
    grid_barrier(base + bar++);

    // ---- per-block constants ----
    const float* __restrict__ msk    = h_masks + layer * Bb * Hh;
    const float* __restrict__ bl     = bias + layer * G4;
    const float* __restrict__ Wint_l = &g_Wint[layer][0][0][0];

    // kgroup split: kg=0 handles k in [0,512) (= vin), kg=1 handles [512,1024) (= h*mask)
    const int kg    = tid >> 8;          // 0 or 1
    const int tid2  = tid & 255;         // thread within kgroup
    const int koff  = kg * 512;
    float* const kgsm = smem + kg * KG_STRIDE;

    // A gmem->regs mapping (within kgroup): row aM, 8 k-values at aK8
    const int aM   = tid2 >> 2;
    const int aK8  = (tid2 & 3) * 8;
    const int arow = m0 + aM;
    const int rr   = aM & 15;
    const int mtW  = aM >> 4;
    const int kt2W = aK8 >> 3;
    const float* __restrict__ mskrow = msk + arow * Hh;

    // B cp.async mapping (within kgroup): thread copies 4x16B per tile
    const int bK = tid2 >> 3;            // 0..31 rows
    const int c0col = (tid2 & 7) * 8;
    int bcoloff[4];
    uint32_t bdstoff[4];
#pragma unroll
    for (int jn = 0; jn < 4; ++jn) {
        const int cc   = c0col + 2 * jn;
        const int gcol = (cc >> 4) * Hh + j0 + (cc & 15);
        bcoloff[jn] = gcol * 2;
        bdstoff[jn] = (uint32_t)((bK * B_ROW_F + cc * 2) * 4);
    }

    // warp / fragment mapping (within kgroup: 8 warps, 2M x 4N)
    const int wwarp = (tid2 >> 5);       // 0..7
    const int lane  = tid & 31;
    const int g     = lane >> 2;
    const int tg    = lane & 3;
    const int warpN = (wwarp & 3) * 16;
    const int mtB   = (wwarp >> 2) * 2;

    const uint32_t sm_base = (uint32_t)__cvta_generic_to_shared(smem);
    const uint32_t kg_base = sm_base + (uint32_t)(kg * KG_STRIDE * 4);

    // epilogue mapping + register state: 2 elements per thread
    const int em    = tid >> 3;          // 0..63
    const int ejj0  = (tid & 7) * 2;     // 0..14 step 2
    const int ebrow = m0 + em;
    const int elen  = lengths[ebrow];
    float bi[2], bf[2], bg[2], bo[2], cR[2], hR[2];
#pragma unroll
    for (int e = 0; e < 2; ++e) {
        const int j = j0 + ejj0 + e;
        bi[e] = bl[j];           bf[e] = bl[Hh + j];
        bg[e] = bl[2 * Hh + j];  bo[e] = bl[3 * Hh + j];
        cR[e] = c0[layer * Bb * Hh + ebrow * Hh + j];
        hR[e] = h0[layer * Bb * Hh + ebrow * Hh + j];
    }

    for (int s = 0; s <= Tt; ++s) {
        const int t = (layer == 0) ? s : (s - 1);
        if (t >= 0 && t < Tt) {
            const float* __restrict__ hin  = &g_h[layer][t & 1][0][0];
            float*       __restrict__ hout = &g_h[layer][(t + 1) & 1][0][0];
            const float* __restrict__ vin;
            size_t vstride;
            if (layer == 0) { vin = x + (size_t)t * Dd; vstride = (size_t)Tt * Dd; }
            else            { vin = &g_hbuf[t & 1][0][0]; vstride = Hh; }

            float acc[2][2][4];
#pragma unroll
            for (int i = 0; i < 2; ++i)
#pragma unroll
                for (int j = 0; j < 2; ++j)
#pragma unroll
                    for (int r = 0; r < 4; ++r) acc[i][j][r] = 0.0f;

            float4 rA0, rA1;
            // --- A register load: kg0 reads vin, kg1 reads h*mask (static!) ---
            auto loadA = [&](int kb) {
                const int k = kb + aK8;   // 0..511 within kgroup
                if (kg == 0) {
                    const float* p = vin + (size_t)arow * vstride + k;
                    rA0 = __ldcg((const float4*)p);
                    rA1 = __ldcg((const float4*)(p + 4));
                } else {
                    const float* hp = hin + arow * Hh + k;
                    const float4 hv0 = __ldcg((const float4*)hp);
                    const float4 hv1 = __ldcg((const float4*)(hp + 4));
                    const float4 mv0 = *(const float4*)(mskrow + k);
                    const float4 mv1 = *(const float4*)(mskrow + k + 4);
                    rA0 = make_float4(hv0.x * mv0.x, hv0.y * mv0.y, hv0.z * mv0.z, hv0.w * mv0.w);
                    rA1 = make_float4(hv1.x * mv1.x, hv1.y * mv1.y, hv1.z * mv1.z, hv1.w * mv1.w);
                }
            };
            auto storeA = [&](int buf) {
                float vals[8] = {rA0.x, rA0.y, rA0.z, rA0.w, rA1.x, rA1.y, rA1.z, rA1.w};
                float* Adst = kgsm + buf * A_BUF_F + (mtW * 4 + kt2W) * A_TILE_F;
#pragma unroll
                for (int i = 0; i < 8; ++i) {
                    const float hi = tf32f(vals[i]);
                    const float lo = tf32f(vals[i] - hi);
                    const int laneW = (rr & 7) * 4 + (i & 3);
                    const int sl    = ((i & 4) >> 1) | (rr >> 3);
                    *(float2*)(Adst + laneW * 12 + sl * 2) = make_float2(hi, lo);
                }
            };
            auto issueB = [&](int kb, int buf) {
                const uint32_t bd = kg_base + (uint32_t)((OFF_B0 + buf * B_BUF_F) * 4);
                const float* srcrow = Wint_l + ((size_t)(koff + kb + bK) * G4) * 2;
#pragma unroll
                for (int jn = 0; jn < 4; ++jn)
                    cpa16(bd + bdstoff[jn], srcrow + bcoloff[jn]);
                asm volatile("cp.async.commit_group;" ::: "memory");
            };

            // ---- prologue: tile 0 ----
            loadA(0);
            issueB(0, 0);
            storeA(0);

#pragma unroll 2
            for (int kt = 0; kt < NT2; ++kt) {
                const int cur = kt & 1;
                const int nxt = cur ^ 1;
                const bool hn = (kt + 1 < NT2);
                if (hn) loadA((kt + 1) * KT);
                asm volatile("cp.async.wait_group 0;" ::: "memory");
                __syncthreads();
                if (hn) issueB((kt + 1) * KT, nxt);

                const float* Acur = kgsm + cur * A_BUF_F;
                const float* Bcur = kgsm + OFF_B0 + cur * B_BUF_F;
#pragma unroll
                for (int kt2 = 0; kt2 < 4; ++kt2) {
                    uint32_t a_h[2][4], a_l[2][4], b_h[2][2], b_l[2][2];
#pragma unroll
                    for (int mt = 0; mt < 2; ++mt) {
                        const float* ap = Acur + ((mtB + mt) * 4 + kt2) * A_TILE_F + lane * 12;
                        const float4 f0 = *(const float4*)ap;
                        const float4 f1 = *(const float4*)(ap + 4);
                        a_h[mt][0] = __float_as_uint(f0.x); a_l[mt][0] = __float_as_uint(f0.y);
                        a_h[mt][1] = __float_as_uint(f0.z); a_l[mt][1] = __float_as_uint(f0.w);
                        a_h[mt][2] = __float_as_uint(f1.x); a_l[mt][2] = __float_as_uint(f1.y);
                        a_h[mt][3] = __float_as_uint(f1.z); a_l[mt][3] = __float_as_uint(f1.w);
                    }
#pragma unroll
                    for (int nt = 0; nt < 2; ++nt) {
                        const float* bp = Bcur + (kt2 * 8 + tg) * B_ROW_F + (warpN + nt * 8 + g) * 2;
                        const float2 v0 = *(const float2*)bp;
                        const float2 v1 = *(const float2*)(bp + 4 * B_ROW_F);
                        b_h[nt][0] = __float_as_uint(v0.x); b_l[nt][0] = __float_as_uint(v0.y);
                        b_h[nt][1] = __float_as_uint(v1.x); b_l[nt][1] = __float_as_uint(v1.y);
                    }
#pragma unroll
                    for (int mt = 0; mt < 2; ++mt)
#pragma unroll
                        for (int nt = 0; nt < 2; ++nt) {
                            mma8(acc[mt][nt], a_h[mt], b_l[nt]);
                            mma8(acc[mt][nt], a_l[mt], b_h[nt]);
                            mma8(acc[mt][nt], a_h[mt], b_h[nt]);
                        }
                }
                if (hn) storeA(nxt);
            }
            __syncthreads();   // all fragment reads done; Zs aliases kgroup0 A region

            // ---- fragment -> Zs regroup: two partial buffers, summed in epilogue ----
            float* Zp = smem + kg * (BM * ZST);   // Zs0 at 0, Zs1 at 4352
            const int warpM = (wwarp >> 2) * 32;
#pragma unroll
            for (int mt = 0; mt < 2; ++mt)
#pragma unroll
                for (int nt = 0; nt < 2; ++nt) {
                    const int r  = warpM + mt * 16 + g;
                    const int cl = warpN + nt * 8 + tg * 2;
                    Zp[r * ZST + cl]           = acc[mt][nt][0];
                    Zp[r * ZST + cl + 1]       = acc[mt][nt][1];
                    Zp[(r + 8) * ZST + cl]     = acc[mt][nt][2];
                    Zp[(r + 8) * ZST + cl + 1] = acc[mt][nt][3];
                }
            __syncthreads();

            // ---- epilogue (c, h register-resident; 2 outputs per thread) ----
            const float* Z0 = smem;
            const float* Z1 = smem + BM * ZST;
            const bool keep = (t < elen);
            float* houtRow = hout + ebrow * Hh;
#pragma unroll
            for (int e = 0; e < 2; ++e) {
                const int jj = ejj0 + e;
                const int j  = j0 + jj;
                const float zi = Z0[em * ZST + jj]      + Z1[em * ZST + jj]      + bi[e];
                const float zf = Z0[em * ZST + 16 + jj] + Z1[em * ZST + 16 + jj] + bf[e];
                const float zg = Z0[em * ZST + 32 + jj] + Z1[em * ZST + 32 + jj] + bg[e];
                const float zo = Z0[em * ZST + 48 + jj] + Z1[em * ZST + 48 + jj] + bo[e];

                const float ig = sigf(zi);
                const float fg = sigf(zf);
                const float gg = tanhf(zg);
                const float og = sigf(zo);

                const float nc = fg * cR[e] + ig * gg;
                const float nh = og * tanhf(nc);

                const float hc = keep ? nh : hR[e];
                cR[e] = keep ? nc : cR[e];
                hR[e] = hc;
                houtRow[j] = hc;

                if (layer == 0) {
                    g_hbuf[s & 1][ebrow][j] = nh;                 // unmasked nh feeds layer 1
                } else {
                    out[((size_t)ebrow * Tt + t) * Hh + j] = nh;  // top-layer output
                }
            }
        }
        grid_barrier(base + bar++);
    }
}

extern "C" void kernel_launch(void* const* d_in, const int* in_sizes, int n_in,
                              void* d_out, int out_size) {
    const float* x       = (const float*)d_in[0];
    const float* h_masks = (const float*)d_in[1];
    const float* Wi      = (const float*)d_in[2];
    const float* Wh      = (const float*)d_in[3];
    const float* bias    = (const float*)d_in[4];
    const float* c0      = (const float*)d_in[5];
    const float* h0      = (const float*)d_in[6];
    const int*   lengths = (const int*)d_in[7];
    float* out = (float*)d_out;

    (void)in_sizes; (void)n_in; (void)out_size;

    cudaFuncSetAttribute(lstm_persistent,
                         cudaFuncAttributeMaxDynamicSharedMemorySize, SMEM_BYTES);

    dim3 grid(Hh / NH, Bb / BM, Ll);  // (32, 2, 2) = 128 blocks, one wave
    lstm_persistent<<<grid, THREADS, SMEM_BYTES>>>(x, h_masks, Wi, Wh, bias, c0, h0, lengths, out);
}

// round 9
// speedup vs baseline: 1.0007x; 1.0007x over previous
#include <cuda_runtime.h>
#include <math.h>
#include <stdint.h>

// Problem constants
#define Bb 128
#define Tt 1024
#define Ll 2
#define Dd 512
#define Hh 512
#define G4 2048   // 4*H
#define Kc 1024   // combined K = D + H

// Tile config
#define BM 64
#define NH 16
#define BN 64
#define KT 32
#define NT2 16           // k-iterations per kgroup (512 / 32)
#define NBLOCKS 128
#define ZST 68
#define THREADS 512

// Shared memory layout (floats), dynamic
#define A_TILE_F 392               // per m16xk8 tile: 32 lanes * 12 (+ pad)
#define A_BUF_F  (16 * A_TILE_F)   // 16 tiles (4 m16 x 4 k8) = 6272
#define B_ROW_F  136               // 64 cols * 2 (hi,lo) + 8 pad
#define B_BUF_F  (KT * B_ROW_F)    // 4352
#define OFF_B0   (2 * A_BUF_F)     // 12544 (within a kgroup region)
#define KG_STRIDE (2 * A_BUF_F + 2 * B_BUF_F)   // 21248 floats per kgroup
#define SMEM_F   (2 * KG_STRIDE)                // 42496 floats
#define SMEM_BYTES (SMEM_F * 4)                 // 169984 B

// Persistent device state
__device__ float g_h[Ll][2][Bb][Hh];      // double-buffered h (parity = t&1 in)
__device__ float g_hbuf[2][Bb][Hh];       // layer-0 unmasked nh stream
__device__ float g_Wint[Ll][Kc][G4][2];   // weights, tf32 {hi,lo} interleaved
__device__ unsigned int g_bar_count;
__device__ unsigned int g_bar_phase;

__device__ __forceinline__ float sigf(float v) { return 1.0f / (1.0f + __expf(-v)); }

__device__ __forceinline__ float tf32f(float x) {
    uint32_t u;
    asm("cvt.rna.tf32.f32 %0, %1;" : "=r"(u) : "f"(x));
    return __uint_as_float(u);
}

__device__ __forceinline__ void mma8(float* c, const uint32_t* a, const uint32_t* b) {
    asm volatile(
        "mma.sync.aligned.m16n8k8.row.col.f32.tf32.tf32.f32 "
        "{%0,%1,%2,%3}, {%4,%5,%6,%7}, {%8,%9}, {%0,%1,%2,%3};"
        : "+f"(c[0]), "+f"(c[1]), "+f"(c[2]), "+f"(c[3])
        : "r"(a[0]), "r"(a[1]), "r"(a[2]), "r"(a[3]), "r"(b[0]), "r"(b[1]));
}

__device__ __forceinline__ void cpa16(uint32_t dst, const void* src) {
    asm volatile("cp.async.cg.shared.global [%0], [%1], 16;" :: "r"(dst), "l"(src));
}

__device__ __forceinline__ void grid_barrier(unsigned int target) {
    __syncthreads();
    if (threadIdx.x == 0) {
        __threadfence();
        unsigned int old = atomicAdd(&g_bar_count, 1u);
        if (old == NBLOCKS - 1) {
            g_bar_count = 0;
            __threadfence();
            atomicAdd(&g_bar_phase, 1u);
        } else {
            while (*(volatile unsigned int*)&g_bar_phase < target) { }
            __threadfence();
        }
    }
    __syncthreads();
}

extern __shared__ float smem[];

__global__ void __launch_bounds__(THREADS, 1)
lstm_persistent(const float* __restrict__ x,
                const float* __restrict__ h_masks,
                const float* __restrict__ Wi,
                const float* __restrict__ Wh,
                const float* __restrict__ bias,
                const float* __restrict__ c0,
                const float* __restrict__ h0,
                const int*   __restrict__ lengths,
                float* __restrict__ out)
{
    __shared__ unsigned int s_base;

    const int tid   = threadIdx.x;
    const int layer = blockIdx.z;
    const int j0    = blockIdx.x * NH;
    const int m0    = blockIdx.y * BM;
    const int gb    = (blockIdx.z * gridDim.y + blockIdx.y) * gridDim.x + blockIdx.x;
    const int gtid  = gb * THREADS + tid;

    if (tid == 0) s_base = *(volatile unsigned int*)&g_bar_phase;

    // ---- one-time init: h state + interleaved split weights ----
    {
        const int total = Ll * Bb * Hh;
        for (int i = gtid; i < total; i += NBLOCKS * THREADS) {
            const int l = i / (Bb * Hh);
            const int r = i % (Bb * Hh);
            (&g_h[l][0][0][0])[r] = h0[i];
        }
        float* Wflat = &g_Wint[0][0][0][0];
        const int totalW = Ll * Kc * G4;   // 2^22
        for (int i = gtid; i < totalW; i += NBLOCKS * THREADS) {
            const int l = i >> 21;
            const int r = i & ((1 << 21) - 1);
            const int k = r >> 11;
            const int c = r & (G4 - 1);
            float w = (k < Dd) ? Wi[(size_t)l * Dd * G4 + (size_t)k * G4 + c]
                               : Wh[(size_t)l * Hh * G4 + (size_t)(k - Dd) * G4 + c];
            float hi = tf32f(w);
            *(float2*)(Wflat + (size_t)i * 2) = make_float2(hi, tf32f(w - hi));
        }
    }
    __syncthreads();
    const unsigned int base = s_base;
    unsigned int bar = 1;
    grid_barrier(base + bar++);

    // ---- per-block constants ----
    const float* __restrict__ msk    = h_masks + layer * Bb * Hh;
    const float* __restrict__ bl     = bias + layer * G4;
    const float* __restrict__ Wint_l = &g_Wint[layer][0][0][0];

    // kgroup split: kg=0 handles k in [0,512) (= vin), kg=1 handles [512,1024) (= h*mask)
    const int kg    = tid >> 8;          // 0 or 1
    const int tid2  = tid & 255;         // thread within kgroup
    const int koff  = kg * 512;
    float* const kgsm = smem + kg * KG_STRIDE;

    // A gmem->regs mapping (within kgroup): row aM, 8 k-values at aK8
    const int aM   = tid2 >> 2;
    const int aK8  = (tid2 & 3) * 8;
    const int arow = m0 + aM;
    const int rr   = aM & 15;
    const int mtW  = aM >> 4;
    const int kt2W = aK8 >> 3;
    const float* __restrict__ mskrow = msk + arow * Hh;

    // B cp.async mapping (within kgroup): thread copies 4x16B per tile
    const int bK = tid2 >> 3;            // 0..31 rows
    const int c0col = (tid2 & 7) * 8;
    int bcoloff[4];
    uint32_t bdstoff[4];
#pragma unroll
    for (int jn = 0; jn < 4; ++jn) {
        const int cc   = c0col + 2 * jn;
        const int gcol = (cc >> 4) * Hh + j0 + (cc & 15);
        bcoloff[jn] = gcol * 2;
        bdstoff[jn] = (uint32_t)((bK * B_ROW_F + cc * 2) * 4);
    }

    // warp / fragment mapping (within kgroup: 8 warps, 2M x 4N)
    const int wwarp = (tid2 >> 5);       // 0..7
    const int lane  = tid & 31;
    const int g     = lane >> 2;
    const int tg    = lane & 3;
    const int warpN = (wwarp & 3) * 16;
    const int mtB   = (wwarp >> 2) * 2;

    const uint32_t sm_base = (uint32_t)__cvta_generic_to_shared(smem);
    const uint32_t kg_base = sm_base + (uint32_t)(kg * KG_STRIDE * 4);

    // epilogue mapping + register state: 2 elements per thread
    const int em    = tid >> 3;          // 0..63
    const int ejj0  = (tid & 7) * 2;     // 0..14 step 2
    const int ebrow = m0 + em;
    const int elen  = lengths[ebrow];
    float bi[2], bf[2], bg[2], bo[2], cR[2], hR[2];
#pragma unroll
    for (int e = 0; e < 2; ++e) {
        const int j = j0 + ejj0 + e;
        bi[e] = bl[j];           bf[e] = bl[Hh + j];
        bg[e] = bl[2 * Hh + j];  bo[e] = bl[3 * Hh + j];
        cR[e] = c0[layer * Bb * Hh + ebrow * Hh + j];
        hR[e] = h0[layer * Bb * Hh + ebrow * Hh + j];
    }

    for (int s = 0; s <= Tt; ++s) {
        const int t = (layer == 0) ? s : (s - 1);
        if (t >= 0 && t < Tt) {
            const float* __restrict__ hin  = &g_h[layer][t & 1][0][0];
            float*       __restrict__ hout = &g_h[layer][(t + 1) & 1][0][0];
            const float* __restrict__ vin;
            size_t vstride;
            if (layer == 0) { vin = x + (size_t)t * Dd; vstride = (size_t)Tt * Dd; }
            else            { vin = &g_hbuf[t & 1][0][0]; vstride = Hh; }

            float acc[2][2][4];
#pragma unroll
            for (int i = 0; i < 2; ++i)
#pragma unroll
                for (int j = 0; j < 2; ++j)
#pragma unroll
                    for (int r = 0; r < 4; ++r) acc[i][j][r] = 0.0f;

            float4 rA0, rA1;
            // --- A register load: kg0 reads vin, kg1 reads h*mask (static!) ---
            auto loadA = [&](int kb) {
                const int k = kb + aK8;   // 0..511 within kgroup
                if (kg == 0) {
                    const float* p = vin + (size_t)arow * vstride + k;
                    rA0 = __ldcg((const float4*)p);
                    rA1 = __ldcg((const float4*)(p + 4));
                } else {
                    const float* hp = hin + arow * Hh + k;
                    const float4 hv0 = __ldcg((const float4*)hp);
                    const float4 hv1 = __ldcg((const float4*)(hp + 4));
                    const float4 mv0 = *(const float4*)(mskrow + k);
                    const float4 mv1 = *(const float4*)(mskrow + k + 4);
                    rA0 = make_float4(hv0.x * mv0.x, hv0.y * mv0.y, hv0.z * mv0.z, hv0.w * mv0.w);
                    rA1 = make_float4(hv1.x * mv1.x, hv1.y * mv1.y, hv1.z * mv1.z, hv1.w * mv1.w);
                }
            };
            auto storeA = [&](int buf) {
                float vals[8] = {rA0.x, rA0.y, rA0.z, rA0.w, rA1.x, rA1.y, rA1.z, rA1.w};
                float* Adst = kgsm + buf * A_BUF_F + (mtW * 4 + kt2W) * A_TILE_F;
#pragma unroll
                for (int i = 0; i < 8; ++i) {
                    const float hi = tf32f(vals[i]);
                    const float lo = tf32f(vals[i] - hi);
                    const int laneW = (rr & 7) * 4 + (i & 3);
                    const int sl    = ((i & 4) >> 1) | (rr >> 3);
                    *(float2*)(Adst + laneW * 12 + sl * 2) = make_float2(hi, lo);
                }
            };
            auto issueB = [&](int kb, int buf) {
                const uint32_t bd = kg_base + (uint32_t)((OFF_B0 + buf * B_BUF_F) * 4);
                const float* srcrow = Wint_l + ((size_t)(koff + kb + bK) * G4) * 2;
#pragma unroll
                for (int jn = 0; jn < 4; ++jn)
                    cpa16(bd + bdstoff[jn], srcrow + bcoloff[jn]);
                asm volatile("cp.async.commit_group;" ::: "memory");
            };

            // ---- prologue: tile 0 ----
            loadA(0);
            issueB(0, 0);
            storeA(0);

#pragma unroll 2
            for (int kt = 0; kt < NT2; ++kt) {
                const int cur = kt & 1;
                const int nxt = cur ^ 1;
                const bool hn = (kt + 1 < NT2);
                if (hn) loadA((kt + 1) * KT);
                asm volatile("cp.async.wait_group 0;" ::: "memory");
                __syncthreads();
                if (hn) issueB((kt + 1) * KT, nxt);

                const float* Acur = kgsm + cur * A_BUF_F;
                const float* Bcur = kgsm + OFF_B0 + cur * B_BUF_F;
#pragma unroll
                for (int kt2 = 0; kt2 < 4; ++kt2) {
                    uint32_t a_h[2][4], a_l[2][4], b_h[2][2], b_l[2][2];
#pragma unroll
                    for (int mt = 0; mt < 2; ++mt) {
                        const float* ap = Acur + ((mtB + mt) * 4 + kt2) * A_TILE_F + lane * 12;
                        const float4 f0 = *(const float4*)ap;
                        const float4 f1 = *(const float4*)(ap + 4);
                        a_h[mt][0] = __float_as_uint(f0.x); a_l[mt][0] = __float_as_uint(f0.y);
                        a_h[mt][1] = __float_as_uint(f0.z); a_l[mt][1] = __float_as_uint(f0.w);
                        a_h[mt][2] = __float_as_uint(f1.x); a_l[mt][2] = __float_as_uint(f1.y);
                        a_h[mt][3] = __float_as_uint(f1.z); a_l[mt][3] = __float_as_uint(f1.w);
                    }
#pragma unroll
                    for (int nt = 0; nt < 2; ++nt) {
                        const float* bp = Bcur + (kt2 * 8 + tg) * B_ROW_F + (warpN + nt * 8 + g) * 2;
                        const float2 v0 = *(const float2*)bp;
                        const float2 v1 = *(const float2*)(bp + 4 * B_ROW_F);
                        b_h[nt][0] = __float_as_uint(v0.x); b_l[nt][0] = __float_as_uint(v0.y);
                        b_h[nt][1] = __float_as_uint(v1.x); b_l[nt][1] = __float_as_uint(v1.y);
                    }
#pragma unroll
                    for (int mt = 0; mt < 2; ++mt)
#pragma unroll
                        for (int nt = 0; nt < 2; ++nt) {
                            mma8(acc[mt][nt], a_h[mt], b_l[nt]);
                            mma8(acc[mt][nt], a_l[mt], b_h[nt]);
                            mma8(acc[mt][nt], a_h[mt], b_h[nt]);
                        }
                }
                if (hn) storeA(nxt);
            }
            __syncthreads();   // all fragment reads done; Zs aliases kgroup0 A region

            // ---- fragment -> Zs regroup: two partial buffers, summed in epilogue ----
            float* Zp = smem + kg * (BM * ZST);   // Zs0 at 0, Zs1 at 4352
            const int warpM = (wwarp >> 2) * 32;
#pragma unroll
            for (int mt = 0; mt < 2; ++mt)
#pragma unroll
                for (int nt = 0; nt < 2; ++nt) {
                    const int r  = warpM + mt * 16 + g;
                    const int cl = warpN + nt * 8 + tg * 2;
                    Zp[r * ZST + cl]           = acc[mt][nt][0];
                    Zp[r * ZST + cl + 1]       = acc[mt][nt][1];
                    Zp[(r + 8) * ZST + cl]     = acc[mt][nt][2];
                    Zp[(r + 8) * ZST + cl + 1] = acc[mt][nt][3];
                }
            __syncthreads();

            // ---- epilogue (c, h register-resident; 2 outputs per thread) ----
            const float* Z0 = smem;
            const float* Z1 = smem + BM * ZST;
            const bool keep = (t < elen);
            float* houtRow = hout + ebrow * Hh;
#pragma unroll
            for (int e = 0; e < 2; ++e) {
                const int jj = ejj0 + e;
                const int j  = j0 + jj;
                const float zi = Z0[em * ZST + jj]      + Z1[em * ZST + jj]      + bi[e];
                const float zf = Z0[em * ZST + 16 + jj] + Z1[em * ZST + 16 + jj] + bf[e];
                const float zg = Z0[em * ZST + 32 + jj] + Z1[em * ZST + 32 + jj] + bg[e];
                const float zo = Z0[em * ZST + 48 + jj] + Z1[em * ZST + 48 + jj] + bo[e];

                const float ig = sigf(zi);
                const float fg = sigf(zf);
                const float gg = tanhf(zg);
                const float og = sigf(zo);

                const float nc = fg * cR[e] + ig * gg;
                const float nh = og * tanhf(nc);

                const float hc = keep ? nh : hR[e];
                cR[e] = keep ? nc : cR[e];
                hR[e] = hc;
                houtRow[j] = hc;

                if (layer == 0) {
                    g_hbuf[s & 1][ebrow][j] = nh;                 // unmasked nh feeds layer 1
                } else {
                    out[((size_t)ebrow * Tt + t) * Hh + j] = nh;  // top-layer output
                }
            }
        }
        grid_barrier(base + bar++);
    }
}

extern "C" void kernel_launch(void* const* d_in, const int* in_sizes, int n_in,
                              void* d_out, int out_size) {
    const float* x       = (const float*)d_in[0];
    const float* h_masks = (const float*)d_in[1];
    const float* Wi      = (const float*)d_in[2];
    const float* Wh      = (const float*)d_in[3];
    const float* bias    = (const float*)d_in[4];
    const float* c0      = (const float*)d_in[5];
    const float* h0      = (const float*)d_in[6];
    const int*   lengths = (const int*)d_in[7];
    float* out = (float*)d_out;

    (void)in_sizes; (void)n_in; (void)out_size;

    cudaFuncSetAttribute(lstm_persistent,
                         cudaFuncAttributeMaxDynamicSharedMemorySize, SMEM_BYTES);

    dim3 grid(Hh / NH, Bb / BM, Ll);  // (32, 2, 2) = 128 blocks, one wave
    lstm_persistent<<<grid, THREADS, SMEM_BYTES>>>(x, h_masks, Wi, Wh, bias, c0, h0, lengths, out);
}

// round 10
// speedup vs baseline: 1.0014x; 1.0007x over previous
#include <cuda_runtime.h>
#include <math.h>
#include <stdint.h>

// Problem constants
#define Bb 128
#define Tt 1024
#define Ll 2
#define Dd 512
#define Hh 512
#define G4 2048   // 4*H
#define Kc 1024   // combined K = D + H

// Tile config
#define BM 64
#define NH 16
#define BN 64
#define KT 32
#define NT2 16           // k-iterations per kgroup (512 / 32)
#define NBLOCKS 128
#define ZST 68
#define THREADS 512

// Shared memory layout (floats), dynamic
#define A_TILE_F 392               // per m16xk8 tile: 32 lanes * 12 (+ pad)
#define A_BUF_F  (16 * A_TILE_F)   // 16 tiles (4 m16 x 4 k8) = 6272
#define B_ROW_F  136               // 64 cols * 2 (hi,lo) + 8 pad
#define B_BUF_F  (KT * B_ROW_F)    // 4352
#define OFF_B0   (2 * A_BUF_F)     // 12544 (within a kgroup region)
#define KG_STRIDE (2 * A_BUF_F + 2 * B_BUF_F)   // 21248 floats per kgroup
#define SMEM_F   (2 * KG_STRIDE)                // 42496 floats
#define SMEM_BYTES (SMEM_F * 4)                 // 169984 B

// Persistent device state
__device__ float g_h[Ll][2][Bb][Hh];      // double-buffered h (parity = t&1 in)
__device__ float g_hbuf[2][Bb][Hh];       // layer-0 unmasked nh stream
__device__ float g_Wint[Ll][Kc][G4][2];   // weights, tf32 {hi,lo} interleaved
__device__ unsigned int g_bar_count;
__device__ unsigned int g_bar_phase;

__device__ __forceinline__ float sigf(float v) { return 1.0f / (1.0f + __expf(-v)); }

__device__ __forceinline__ float tf32f(float x) {
    uint32_t u;
    asm("cvt.rna.tf32.f32 %0, %1;" : "=r"(u) : "f"(x));
    return __uint_as_float(u);
}

__device__ __forceinline__ void mma8(float* c, const uint32_t* a, const uint32_t* b) {
    asm volatile(
        "mma.sync.aligned.m16n8k8.row.col.f32.tf32.tf32.f32 "
        "{%0,%1,%2,%3}, {%4,%5,%6,%7}, {%8,%9}, {%0,%1,%2,%3};"
        : "+f"(c[0]), "+f"(c[1]), "+f"(c[2]), "+f"(c[3])
        : "r"(a[0]), "r"(a[1]), "r"(a[2]), "r"(a[3]), "r"(b[0]), "r"(b[1]));
}

__device__ __forceinline__ void cpa16(uint32_t dst, const void* src) {
    asm volatile("cp.async.cg.shared.global [%0], [%1], 16;" :: "r"(dst), "l"(src));
}

__device__ __forceinline__ void grid_barrier(unsigned int target) {
    __syncthreads();
    if (threadIdx.x == 0) {
        __threadfence();
        unsigned int old = atomicAdd(&g_bar_count, 1u);
        if (old == NBLOCKS - 1) {
            g_bar_count = 0;
            __threadfence();
            atomicAdd(&g_bar_phase, 1u);
        } else {
            while (*(volatile unsigned int*)&g_bar_phase < target) { }
            __threadfence();
        }
    }
    __syncthreads();
}

extern __shared__ float smem[];

__global__ void __launch_bounds__(THREADS, 1)
lstm_persistent(const float* __restrict__ x,
                const float* __restrict__ h_masks,
                const float* __restrict__ Wi,
                const float* __restrict__ Wh,
                const float* __restrict__ bias,
                const float* __restrict__ c0,
                const float* __restrict__ h0,
                const int*   __restrict__ lengths,
                float* __restrict__ out)
{
    __shared__ unsigned int s_base;

    const int tid   = threadIdx.x;
    const int layer = blockIdx.z;
    const int j0    = blockIdx.x * NH;
    const int m0    = blockIdx.y * BM;
    const int gb    = (blockIdx.z * gridDim.y + blockIdx.y) * gridDim.x + blockIdx.x;
    const int gtid  = gb * THREADS + tid;

    if (tid == 0) s_base = *(volatile unsigned int*)&g_bar_phase;

    // ---- one-time init: h state + interleaved split weights ----
    {
        const int total = Ll * Bb * Hh;
        for (int i = gtid; i < total; i += NBLOCKS * THREADS) {
            const int l = i / (Bb * Hh);
            const int r = i % (Bb * Hh);
            (&g_h[l][0][0][0])[r] = h0[i];
        }
        float* Wflat = &g_Wint[0][0][0][0];
        const int totalW = Ll * Kc * G4;   // 2^22
        for (int i = gtid; i < totalW; i += NBLOCKS * THREADS) {
            const int l = i >> 21;
            const int r = i & ((1 << 21) - 1);
            const int k = r >> 11;
            const int c = r & (G4 - 1);
            float w = (k < Dd) ? Wi[(size_t)l * Dd * G4 + (size_t)k * G4 + c]
                               : Wh[(size_t)l * Hh * G4 + (size_t)(k - Dd) * G4 + c];
            float hi = tf32f(w);
            *(float2*)(Wflat + (size_t)i * 2) = make_float2(hi, tf32f(w - hi));
        }
    }
    __syncthreads();
    const unsigned int base = s_base;
    unsigned int bar = 1;
    grid_barrier(base + bar++);

    // ---- per-block constants ----
    const float* __restrict__ msk    = h_masks + layer * Bb * Hh;
    const float* __restrict__ bl     = bias + layer * G4;
    const float* __restrict__ Wint_l = &g_Wint[layer][0][0][0];

    // kgroup split: kg=0 handles k in [0,512) (= vin), kg=1 handles [512,1024) (= h*mask)
    const int kg    = tid >> 8;          // 0 or 1
    const int tid2  = tid & 255;         // thread within kgroup
    const int koff  = kg * 512;
    float* const kgsm = smem + kg * KG_STRIDE;

    // A gmem->regs mapping (within kgroup): row aM, 8 k-values at aK8
    const int aM   = tid2 >> 2;
    const int aK8  = (tid2 & 3) * 8;
    const int arow = m0 + aM;
    const int rr   = aM & 15;
    const int mtW  = aM >> 4;
    const int kt2W = aK8 >> 3;
    const float* __restrict__ mskrow = msk + arow * Hh;

    // B cp.async mapping (within kgroup): thread copies 4x16B per tile
    const int bK = tid2 >> 3;            // 0..31 rows
    const int c0col = (tid2 & 7) * 8;
    int bcoloff[4];
    uint32_t bdstoff[4];
#pragma unroll
    for (int jn = 0; jn < 4; ++jn) {
        const int cc   = c0col + 2 * jn;
        const int gcol = (cc >> 4) * Hh + j0 + (cc & 15);
        bcoloff[jn] = gcol * 2;
        bdstoff[jn] = (uint32_t)((bK * B_ROW_F + cc * 2) * 4);
    }

    // warp / fragment mapping (within kgroup: 8 warps, 2M x 4N)
    const int wwarp = (tid2 >> 5);       // 0..7
    const int lane  = tid & 31;
    const int g     = lane >> 2;
    const int tg    = lane & 3;
    const int warpN = (wwarp & 3) * 16;
    const int mtB   = (wwarp >> 2) * 2;

    const uint32_t sm_base = (uint32_t)__cvta_generic_to_shared(smem);
    const uint32_t kg_base = sm_base + (uint32_t)(kg * KG_STRIDE * 4);

    // epilogue mapping + register state: 2 elements per thread
    const int em    = tid >> 3;          // 0..63
    const int ejj0  = (tid & 7) * 2;     // 0..14 step 2
    const int ebrow = m0 + em;
    const int elen  = lengths[ebrow];
    float bi[2], bf[2], bg[2], bo[2], cR[2], hR[2];
#pragma unroll
    for (int e = 0; e < 2; ++e) {
        const int j = j0 + ejj0 + e;
        bi[e] = bl[j];           bf[e] = bl[Hh + j];
        bg[e] = bl[2 * Hh + j];  bo[e] = bl[3 * Hh + j];
        cR[e] = c0[layer * Bb * Hh + ebrow * Hh + j];
        hR[e] = h0[layer * Bb * Hh + ebrow * Hh + j];
    }

    for (int s = 0; s <= Tt; ++s) {
        const int t = (layer == 0) ? s : (s - 1);
        if (t >= 0 && t < Tt) {
            const float* __restrict__ hin  = &g_h[layer][t & 1][0][0];
            float*       __restrict__ hout = &g_h[layer][(t + 1) & 1][0][0];
            const float* __restrict__ vin;
            size_t vstride;
            if (layer == 0) { vin = x + (size_t)t * Dd; vstride = (size_t)Tt * Dd; }
            else            { vin = &g_hbuf[t & 1][0][0]; vstride = Hh; }

            float acc[2][2][4];
#pragma unroll
            for (int i = 0; i < 2; ++i)
#pragma unroll
                for (int j = 0; j < 2; ++j)
#pragma unroll
                    for (int r = 0; r < 4; ++r) acc[i][j][r] = 0.0f;

            float4 rA0, rA1;
            // --- A register load: kg0 reads vin, kg1 reads h*mask (static!) ---
            auto loadA = [&](int kb) {
                const int k = kb + aK8;   // 0..511 within kgroup
                if (kg == 0) {
                    const float* p = vin + (size_t)arow * vstride + k;
                    rA0 = __ldcg((const float4*)p);
                    rA1 = __ldcg((const float4*)(p + 4));
                } else {
                    const float* hp = hin + arow * Hh + k;
                    const float4 hv0 = __ldcg((const float4*)hp);
                    const float4 hv1 = __ldcg((const float4*)(hp + 4));
                    const float4 mv0 = *(const float4*)(mskrow + k);
                    const float4 mv1 = *(const float4*)(mskrow + k + 4);
                    rA0 = make_float4(hv0.x * mv0.x, hv0.y * mv0.y, hv0.z * mv0.z, hv0.w * mv0.w);
                    rA1 = make_float4(hv1.x * mv1.x, hv1.y * mv1.y, hv1.z * mv1.z, hv1.w * mv1.w);
                }
            };
            auto storeA = [&](int buf) {
                float vals[8] = {rA0.x, rA0.y, rA0.z, rA0.w, rA1.x, rA1.y, rA1.z, rA1.w};
                float* Adst = kgsm + buf * A_BUF_F + (mtW * 4 + kt2W) * A_TILE_F;
#pragma unroll
                for (int i = 0; i < 8; ++i) {
                    const float hi = tf32f(vals[i]);
                    const float lo = tf32f(vals[i] - hi);
                    const int laneW = (rr & 7) * 4 + (i & 3);
                    const int sl    = ((i & 4) >> 1) | (rr >> 3);
                    *(float2*)(Adst + laneW * 12 + sl * 2) = make_float2(hi, lo);
                }
            };
            auto issueB = [&](int kb, int buf) {
                const uint32_t bd = kg_base + (uint32_t)((OFF_B0 + buf * B_BUF_F) * 4);
                const float* srcrow = Wint_l + ((size_t)(koff + kb + bK) * G4) * 2;
#pragma unroll
                for (int jn = 0; jn < 4; ++jn)
                    cpa16(bd + bdstoff[jn], srcrow + bcoloff[jn]);
                asm volatile("cp.async.commit_group;" ::: "memory");
            };

            // ---- prologue: tile 0 ----
            loadA(0);
            issueB(0, 0);
            storeA(0);

#pragma unroll 2
            for (int kt = 0; kt < NT2; ++kt) {
                const int cur = kt & 1;
                const int nxt = cur ^ 1;
                const bool hn = (kt + 1 < NT2);
                if (hn) loadA((kt + 1) * KT);
                asm volatile("cp.async.wait_group 0;" ::: "memory");
                __syncthreads();
                if (hn) issueB((kt + 1) * KT, nxt);

                const float* Acur = kgsm + cur * A_BUF_F;
                const float* Bcur = kgsm + OFF_B0 + cur * B_BUF_F;
#pragma unroll
                for (int kt2 = 0; kt2 < 4; ++kt2) {
                    uint32_t a_h[2][4], a_l[2][4], b_h[2][2], b_l[2][2];
#pragma unroll
                    for (int mt = 0; mt < 2; ++mt) {
                        const float* ap = Acur + ((mtB + mt) * 4 + kt2) * A_TILE_F + lane * 12;
                        const float4 f0 = *(const float4*)ap;
                        const float4 f1 = *(const float4*)(ap + 4);
                        a_h[mt][0] = __float_as_uint(f0.x); a_l[mt][0] = __float_as_uint(f0.y);
                        a_h[mt][1] = __float_as_uint(f0.z); a_l[mt][1] = __float_as_uint(f0.w);
                        a_h[mt][2] = __float_as_uint(f1.x); a_l[mt][2] = __float_as_uint(f1.y);
                        a_h[mt][3] = __float_as_uint(f1.z); a_l[mt][3] = __float_as_uint(f1.w);
                    }
#pragma unroll
                    for (int nt = 0; nt < 2; ++nt) {
                        const float* bp = Bcur + (kt2 * 8 + tg) * B_ROW_F + (warpN + nt * 8 + g) * 2;
                        const float2 v0 = *(const float2*)bp;
                        const float2 v1 = *(const float2*)(bp + 4 * B_ROW_F);
                        b_h[nt][0] = __float_as_uint(v0.x); b_l[nt][0] = __float_as_uint(v0.y);
                        b_h[nt][1] = __float_as_uint(v1.x); b_l[nt][1] = __float_as_uint(v1.y);
                    }
#pragma unroll
                    for (int mt = 0; mt < 2; ++mt)
#pragma unroll
                        for (int nt = 0; nt < 2; ++nt) {
                            mma8(acc[mt][nt], a_h[mt], b_l[nt]);
                            mma8(acc[mt][nt], a_l[mt], b_h[nt]);
                            mma8(acc[mt][nt], a_h[mt], b_h[nt]);
                        }
                }
                if (hn) storeA(nxt);
            }
            __syncthreads();   // all fragment reads done; Zs aliases kgroup0 A region

            // ---- fragment -> Zs regroup: two partial buffers, summed in epilogue ----
            float* Zp = smem + kg * (BM * ZST);   // Zs0 at 0, Zs1 at 4352
            const int warpM = (wwarp >> 2) * 32;
#pragma unroll
            for (int mt = 0; mt < 2; ++mt)
#pragma unroll
                for (int nt = 0; nt < 2; ++nt) {
                    const int r  = warpM + mt * 16 + g;
                    const int cl = warpN + nt * 8 + tg * 2;
                    Zp[r * ZST + cl]           = acc[mt][nt][0];
                    Zp[r * ZST + cl + 1]       = acc[mt][nt][1];
                    Zp[(r + 8) * ZST + cl]     = acc[mt][nt][2];
                    Zp[(r + 8) * ZST + cl + 1] = acc[mt][nt][3];
                }
            __syncthreads();

            // ---- epilogue (c, h register-resident; 2 outputs per thread) ----
            const float* Z0 = smem;
            const float* Z1 = smem + BM * ZST;
            const bool keep = (t < elen);
            float* houtRow = hout + ebrow * Hh;
#pragma unroll
            for (int e = 0; e < 2; ++e) {
                const int jj = ejj0 + e;
                const int j  = j0 + jj;
                const float zi = Z0[em * ZST + jj]      + Z1[em * ZST + jj]      + bi[e];
                const float zf = Z0[em * ZST + 16 + jj] + Z1[em * ZST + 16 + jj] + bf[e];
                const float zg = Z0[em * ZST + 32 + jj] + Z1[em * ZST + 32 + jj] + bg[e];
                const float zo = Z0[em * ZST + 48 + jj] + Z1[em * ZST + 48 + jj] + bo[e];

                const float ig = sigf(zi);
                const float fg = sigf(zf);
                const float gg = tanhf(zg);
                const float og = sigf(zo);

                const float nc = fg * cR[e] + ig * gg;
                const float nh = og * tanhf(nc);

                const float hc = keep ? nh : hR[e];
                cR[e] = keep ? nc : cR[e];
                hR[e] = hc;
                houtRow[j] = hc;

                if (layer == 0) {
                    g_hbuf[s & 1][ebrow][j] = nh;                 // unmasked nh feeds layer 1
                } else {
                    out[((size_t)ebrow * Tt + t) * Hh + j] = nh;  // top-layer output
                }
            }
        }
        grid_barrier(base + bar++);
    }
}

extern "C" void kernel_launch(void* const* d_in, const int* in_sizes, int n_in,
                              void* d_out, int out_size) {
    const float* x       = (const float*)d_in[0];
    const float* h_masks = (const float*)d_in[1];
    const float* Wi      = (const float*)d_in[2];
    const float* Wh      = (const float*)d_in[3];
    const float* bias    = (const float*)d_in[4];
    const float* c0      = (const float*)d_in[5];
    const float* h0      = (const float*)d_in[6];
    const int*   lengths = (const int*)d_in[7];
    float* out = (float*)d_out;

    (void)in_sizes; (void)n_in; (void)out_size;

    cudaFuncSetAttribute(lstm_persistent,
                         cudaFuncAttributeMaxDynamicSharedMemorySize, SMEM_BYTES);

    dim3 grid(Hh / NH, Bb / BM, Ll);  // (32, 2, 2) = 128 blocks, one wave
    lstm_persistent<<<grid, THREADS, SMEM_BYTES>>>(x, h_masks, Wi, Wh, bias, c0, h0, lengths, out);
}